// round 1
// baseline (speedup 1.0000x reference)
#include <cuda_runtime.h>

#define Bm 512
#define Em 256
#define Am 128
#define Km 6
#define Fm 147     // ATOM_FDIM + BOND_FDIM
#define AFm 133
#define Hm 128
#define CATD 261   // AFm + Hm

// scratch (device globals: allocation-free rule)
__device__ float g_inp[Bm * Em * Hm];   // 64 MB
__device__ float g_msgA[Bm * Em * Hm];  // 64 MB
__device__ float g_msgB[Bm * Em * Hm];  // 64 MB
__device__ int   g_off[Bm];

#define FMA2(d, a, b, c) asm("fma.rn.f32x2 %0, %1, %2, %3;" : "=l"(d) : "l"(a), "l"(b), "l"(c))
#define PACK2(d, x)      asm("mov.b64 %0, {%1, %1};"       : "=l"(d) : "f"(x))
#define UNPACK2(x, y, d) asm("mov.b64 {%0, %1}, %2;"       : "=f"(x), "=f"(y) : "l"(d))

// ---------------------------------------------------------------------------
// exclusive scan of mol_lens -> g_off ; write c_mask
// ---------------------------------------------------------------------------
extern "C" __global__ void __launch_bounds__(512) k_scan(const int* __restrict__ ml,
                                                         float* __restrict__ maskbase)
{
    __shared__ int s[512];
    int t = threadIdx.x;
    int v = ml[t];
    s[t] = v;
    __syncthreads();
    for (int off = 1; off < 512; off <<= 1) {
        int u = (t >= off) ? s[t - off] : 0;
        __syncthreads();
        s[t] += u;
        __syncthreads();
    }
    g_off[t] = s[t] - v;  // exclusive prefix
    for (int i = t; i < Bm * Am; i += 512) {
        int b = i >> 7, a = i & 127;
        maskbase[i] = (a < ml[b]) ? 1.0f : 0.0f;
    }
}

// ---------------------------------------------------------------------------
// inp = fin @ Wi^T ; msgA = relu(inp)      rows = B*E = 131072, K = 147
// smem: Wt[147][132] + in_s[64][148]
// ---------------------------------------------------------------------------
extern "C" __global__ void __launch_bounds__(256) k_wi(const float* __restrict__ fin,
                                                       const float* __restrict__ Wi)
{
    extern __shared__ float sm[];
    float* Wt   = sm;             // 147*132
    float* in_s = sm + Fm * 132;  // 64*148
    int tid = threadIdx.x;

    for (int idx = tid; idx < Hm * Fm; idx += 256) {
        int h = idx / Fm, f = idx - h * Fm;
        Wt[f * 132 + h] = Wi[idx];
    }
    int row0 = blockIdx.x * 64;
    for (int idx = tid; idx < 64 * Fm; idx += 256) {
        int r = idx / Fm, f = idx - r * Fm;
        in_s[r * 148 + f] = fin[(size_t)(row0 + r) * Fm + f];
    }
    __syncthreads();

    int r = tid >> 2, cg = tid & 3, cbase = cg * 32;
    unsigned long long acc[16];
#pragma unroll
    for (int i = 0; i < 16; i++) acc[i] = 0ull;
    const float* inrow = in_s + r * 148;

#pragma unroll 2
    for (int k = 0; k < Fm; k++) {
        unsigned long long av;
        PACK2(av, inrow[k]);
        const ulonglong2* w = (const ulonglong2*)(Wt + k * 132 + cbase);
#pragma unroll
        for (int i = 0; i < 8; i++) {
            ulonglong2 wv = w[i];
            FMA2(acc[2 * i],     av, wv.x, acc[2 * i]);
            FMA2(acc[2 * i + 1], av, wv.y, acc[2 * i + 1]);
        }
    }

    float* pi = g_inp  + (size_t)(row0 + r) * Hm + cbase;
    float* pm = g_msgA + (size_t)(row0 + r) * Hm + cbase;
#pragma unroll
    for (int i = 0; i < 16; i++) {
        float x, y;
        UNPACK2(x, y, acc[i]);
        ((float2*)pi)[i] = make_float2(x, y);
        ((float2*)pm)[i] = make_float2(fmaxf(x, 0.f), fmaxf(y, 0.f));
    }
}

// ---------------------------------------------------------------------------
// message passing step: agg = gather_sum(msg_in, mapping);
// msg_out = relu(inp + agg @ Wh^T)         rows = 131072, K = 128
// smem: Wt[128][132] + agg[64][132]
// ---------------------------------------------------------------------------
extern "C" __global__ void __launch_bounds__(256) k_mp(const int* __restrict__ mapping,
                                                       const float* __restrict__ Wh,
                                                       int dir)
{
    const float* msg_in = dir ? g_msgB : g_msgA;
    float*       msg_out = dir ? g_msgA : g_msgB;

    extern __shared__ float sm[];
    float* Wt  = sm;             // 128*132
    float* agg = sm + Hm * 132;  // 64*132
    int tid = threadIdx.x;

    for (int idx = tid; idx < Hm * Hm; idx += 256) {
        int g = idx >> 7, h = idx & 127;
        Wt[h * 132 + g] = Wh[idx];
    }

    int row0 = blockIdx.x * 64;
    int r = tid >> 2, cg = tid & 3, cbase = cg * 32;
    int gr = row0 + r;
    int b = gr >> 8;
    const int* map = mapping + (size_t)gr * Km;

    float4 s[8];
#pragma unroll
    for (int i = 0; i < 8; i++) s[i] = make_float4(0.f, 0.f, 0.f, 0.f);
#pragma unroll
    for (int k = 0; k < Km; k++) {
        int idx = map[k];
        const float4* mr = (const float4*)(msg_in + (size_t)(b * Em + idx) * Hm + cbase);
#pragma unroll
        for (int i = 0; i < 8; i++) {
            float4 v = mr[i];
            s[i].x += v.x; s[i].y += v.y; s[i].z += v.z; s[i].w += v.w;
        }
    }
    float4* ar = (float4*)(agg + r * 132 + cbase);
#pragma unroll
    for (int i = 0; i < 8; i++) ar[i] = s[i];
    __syncthreads();

    unsigned long long acc[16];
#pragma unroll
    for (int i = 0; i < 16; i++) acc[i] = 0ull;
    const float* arow = agg + r * 132;

#pragma unroll 2
    for (int k = 0; k < Hm; k++) {
        unsigned long long av;
        PACK2(av, arow[k]);
        const ulonglong2* w = (const ulonglong2*)(Wt + k * 132 + cbase);
#pragma unroll
        for (int i = 0; i < 8; i++) {
            ulonglong2 wv = w[i];
            FMA2(acc[2 * i],     av, wv.x, acc[2 * i]);
            FMA2(acc[2 * i + 1], av, wv.y, acc[2 * i + 1]);
        }
    }

    const float2* pi = (const float2*)(g_inp + (size_t)gr * Hm + cbase);
    float2* po = (float2*)(msg_out + (size_t)gr * Hm + cbase);
#pragma unroll
    for (int i = 0; i < 16; i++) {
        float x, y;
        UNPACK2(x, y, acc[i]);
        float2 iv = pi[i];
        po[i] = make_float2(fmaxf(iv.x + x, 0.f), fmaxf(iv.y + y, 0.f));
    }
}

// ---------------------------------------------------------------------------
// m2a = gather_sum(msgA, a2b); cat = [atom_feature | m2a];
// atoms_h = relu(cat @ Wo^T + bo); scatter valid rows via g_off
// smem: Wt[261][132] + cat[64][268] + bo[128]
// ---------------------------------------------------------------------------
extern "C" __global__ void __launch_bounds__(256) k_out(const float* __restrict__ af,
                                                        const int* __restrict__ a2b,
                                                        const float* __restrict__ Wo,
                                                        const float* __restrict__ bo,
                                                        const int* __restrict__ ml,
                                                        float* __restrict__ out)
{
    int row0 = blockIdx.x * 64;
    int b = row0 >> 7;
    int a0 = row0 & 127;
    int len = ml[b];
    if (a0 >= len) return;  // uniform per block

    extern __shared__ float sm[];
    float* Wt  = sm;                   // 261*132
    float* cat = sm + CATD * 132;      // 64*268
    float* bs  = cat + 64 * 268;       // 128
    int tid = threadIdx.x;

    if (tid < 128) bs[tid] = bo[tid];
    for (int idx = tid; idx < Hm * CATD; idx += 256) {
        int h = idx / CATD, d = idx - h * CATD;
        Wt[d * 132 + h] = Wo[idx];
    }
    for (int idx = tid; idx < 64 * AFm; idx += 256) {
        int r = idx / AFm, f = idx - r * AFm;
        cat[r * 268 + f] = af[(size_t)(row0 + r) * AFm + f];
    }

    int r = tid >> 2, cg = tid & 3, cbase = cg * 32;
    int gr = row0 + r;
    int a = a0 + r;
    const int* gi = a2b + (size_t)gr * Km;

    float4 s[8];
#pragma unroll
    for (int i = 0; i < 8; i++) s[i] = make_float4(0.f, 0.f, 0.f, 0.f);
#pragma unroll
    for (int k = 0; k < Km; k++) {
        int idx = gi[k];
        const float4* mr = (const float4*)(g_msgA + (size_t)(b * Em + idx) * Hm + cbase);
#pragma unroll
        for (int i = 0; i < 8; i++) {
            float4 v = mr[i];
            s[i].x += v.x; s[i].y += v.y; s[i].z += v.z; s[i].w += v.w;
        }
    }
    float4* cr = (float4*)(cat + r * 268 + 136 + cbase);  // m2a at 136..263
#pragma unroll
    for (int i = 0; i < 8; i++) cr[i] = s[i];
    __syncthreads();

    unsigned long long acc[16];
#pragma unroll
    for (int i = 0; i < 16; i++) acc[i] = 0ull;
    const float* crow = cat + r * 268;

#pragma unroll 2
    for (int k = 0; k < AFm; k++) {   // d = k, features 0..132
        unsigned long long av;
        PACK2(av, crow[k]);
        const ulonglong2* w = (const ulonglong2*)(Wt + k * 132 + cbase);
#pragma unroll
        for (int i = 0; i < 8; i++) {
            ulonglong2 wv = w[i];
            FMA2(acc[2 * i],     av, wv.x, acc[2 * i]);
            FMA2(acc[2 * i + 1], av, wv.y, acc[2 * i + 1]);
        }
    }
#pragma unroll 2
    for (int k = AFm; k < CATD; k++) {  // d = k, m2a at cat col k+3
        unsigned long long av;
        PACK2(av, crow[k + 3]);
        const ulonglong2* w = (const ulonglong2*)(Wt + k * 132 + cbase);
#pragma unroll
        for (int i = 0; i < 8; i++) {
            ulonglong2 wv = w[i];
            FMA2(acc[2 * i],     av, wv.x, acc[2 * i]);
            FMA2(acc[2 * i + 1], av, wv.y, acc[2 * i + 1]);
        }
    }

    if (a < len) {
        float* po = out + (size_t)(g_off[b] + a) * Hm + cbase;
#pragma unroll
        for (int i = 0; i < 16; i++) {
            float x, y;
            UNPACK2(x, y, acc[i]);
            x = fmaxf(x + bs[cbase + 2 * i], 0.f);
            y = fmaxf(y + bs[cbase + 2 * i + 1], 0.f);
            ((float2*)po)[i] = make_float2(x, y);
        }
    }
}

// ---------------------------------------------------------------------------
extern "C" void kernel_launch(void* const* d_in, const int* in_sizes, int n_in,
                              void* d_out, int out_size)
{
    const float* af      = (const float*)d_in[0];  // [B,A,133]
    const float* fin     = (const float*)d_in[1];  // [B,E,147]
    const int*   a2b     = (const int*)d_in[2];    // [B,A,6]
    const int*   mapping = (const int*)d_in[3];    // [B,E,6]
    // d_in[4] = global_f (unused by reference output)
    const int*   ml      = (const int*)d_in[5];    // [B]
    const float* Wi      = (const float*)d_in[6];  // [128,147]
    const float* Wh      = (const float*)d_in[7];  // [128,128]
    const float* Wo      = (const float*)d_in[8];  // [128,261]
    const float* bo      = (const float*)d_in[9];  // [128]
    float* out = (float*)d_out;
    float* maskbase = out + (size_t)out_size - (size_t)Bm * Am;

    int smA = (Fm * 132 + 64 * 148) * 4;
    int smM = (Hm * 132 + 64 * 132) * 4;
    int smO = (CATD * 132 + 64 * 268 + 128) * 4;
    cudaFuncSetAttribute(k_wi,  cudaFuncAttributeMaxDynamicSharedMemorySize, smA);
    cudaFuncSetAttribute(k_mp,  cudaFuncAttributeMaxDynamicSharedMemorySize, smM);
    cudaFuncSetAttribute(k_out, cudaFuncAttributeMaxDynamicSharedMemorySize, smO);

    k_scan<<<1, 512>>>(ml, maskbase);
    k_wi<<<(Bm * Em) / 64, 256, smA>>>(fin, Wi);
    k_mp<<<(Bm * Em) / 64, 256, smM>>>(mapping, Wh, 0);  // msgA -> msgB
    k_mp<<<(Bm * Em) / 64, 256, smM>>>(mapping, Wh, 1);  // msgB -> msgA
    k_out<<<(Bm * Am) / 64, 256, smO>>>(af, a2b, Wo, bo, ml, out);
}

// round 3
// speedup vs baseline: 4.7107x; 4.7107x over previous
#include <cuda_runtime.h>

#define Bm 512
#define Em 256
#define Am 128
#define Km 6
#define Fm 147     // ATOM_FDIM + BOND_FDIM
#define AFm 133
#define Hm 128
#define CATD 261
#define S_IN 149   // ≡5 mod 8: conflict-free 4-row scalar LDS
#define S_AG 133
#define S_CAT 269

// device-global scratch (allocation-free rule)
__device__ float g_inp [Bm * Em * Hm];
__device__ float g_msgA[Bm * Em * Hm];
__device__ float g_msgB[Bm * Em * Hm];
__device__ float g_WiT[Fm * Hm];     // k-major, perm128 column layout
__device__ float g_WhT[Hm * Hm];
__device__ float g_WoT[CATD * Hm];
__device__ int   g_off[Bm];

#define FMA2(d, a, b, c) asm("fma.rn.f32x2 %0, %1, %2, %3;" : "=l"(d) : "l"(a), "l"(b), "l"(c))
#define PACK2(d, x)      asm("mov.b64 %0, {%1, %1};"        : "=l"(d) : "f"(x))
#define UNPACK2(x, y, d) asm("mov.b64 {%0, %1}, %2;"        : "=f"(x), "=f"(y) : "l"(d))

// store column h at position (q, cgi, e): conflict-free 16B windows per k-row
__device__ __forceinline__ int perm128(int h) {
    return (((h >> 2) & 3) << 5) + ((h >> 4) << 2) + (h & 3);
}

// ---------------------------------------------------------------------------
// exclusive scan of mol_lens -> g_off ; write c_mask
// ---------------------------------------------------------------------------
extern "C" __global__ void __launch_bounds__(512) k_scan(const int* __restrict__ ml,
                                                         float* __restrict__ maskbase)
{
    __shared__ int s[512];
    int t = threadIdx.x;
    int v = ml[t];
    s[t] = v;
    __syncthreads();
    for (int off = 1; off < 512; off <<= 1) {
        int u = (t >= off) ? s[t - off] : 0;
        __syncthreads();
        s[t] += u;
        __syncthreads();
    }
    g_off[t] = s[t] - v;
    for (int i = t; i < Bm * Am; i += 512) {
        int b = i >> 7, a = i & 127;
        maskbase[i] = (a < ml[b]) ? 1.0f : 0.0f;
    }
}

// ---------------------------------------------------------------------------
// one-shot weight transpose into k-major permuted layout
// ---------------------------------------------------------------------------
extern "C" __global__ void __launch_bounds__(256) k_tw(const float* __restrict__ Wi,
                                                       const float* __restrict__ Wh,
                                                       const float* __restrict__ Wo)
{
    int i = blockIdx.x * 256 + threadIdx.x;
    if (i < Fm * Hm) {
        int h = i / Fm, k = i - h * Fm;
        g_WiT[k * Hm + perm128(h)] = Wi[i];
    }
    int j = i - Fm * Hm;
    if (j >= 0 && j < Hm * Hm) {
        int h = j >> 7, k = j & 127;
        g_WhT[k * Hm + perm128(h)] = Wh[j];
    }
    int l = i - Fm * Hm - Hm * Hm;
    if (l >= 0 && l < CATD * Hm) {
        int h = l / CATD, k = l - h * CATD;
        g_WoT[k * Hm + perm128(h)] = Wo[l];
    }
}

// ---------------------------------------------------------------------------
// 4-row x 16-col register-tile GEMM inner loop
// acc[i*8+j] holds output cols (c0+2j, c0+2j+1) for row r0+i
// ---------------------------------------------------------------------------
__device__ __forceinline__ void gemm4x16(const float* __restrict__ Wt,
                                         const float* __restrict__ Ar, int S, int K,
                                         int cgi, unsigned long long acc[32])
{
    const float* wbase = Wt + cgi * 4;
#pragma unroll 2
    for (int k = 0; k < K; k++) {
        const float* wrow = wbase + k * Hm;
        ulonglong2 v0 = *(const ulonglong2*)(wrow);
        ulonglong2 v1 = *(const ulonglong2*)(wrow + 32);
        ulonglong2 v2 = *(const ulonglong2*)(wrow + 64);
        ulonglong2 v3 = *(const ulonglong2*)(wrow + 96);
        unsigned long long w0 = v0.x, w1 = v0.y, w2 = v1.x, w3 = v1.y;
        unsigned long long w4 = v2.x, w5 = v2.y, w6 = v3.x, w7 = v3.y;
#pragma unroll
        for (int i = 0; i < 4; i++) {
            unsigned long long av;
            PACK2(av, Ar[i * S + k]);
            FMA2(acc[i * 8 + 0], av, w0, acc[i * 8 + 0]);
            FMA2(acc[i * 8 + 1], av, w1, acc[i * 8 + 1]);
            FMA2(acc[i * 8 + 2], av, w2, acc[i * 8 + 2]);
            FMA2(acc[i * 8 + 3], av, w3, acc[i * 8 + 3]);
            FMA2(acc[i * 8 + 4], av, w4, acc[i * 8 + 4]);
            FMA2(acc[i * 8 + 5], av, w5, acc[i * 8 + 5]);
            FMA2(acc[i * 8 + 6], av, w6, acc[i * 8 + 6]);
            FMA2(acc[i * 8 + 7], av, w7, acc[i * 8 + 7]);
        }
    }
}

// ---------------------------------------------------------------------------
// inp = fin @ Wi^T ; msgA = relu(inp)
// ---------------------------------------------------------------------------
extern "C" __global__ void __launch_bounds__(128) k_wi(const float* __restrict__ fin)
{
    extern __shared__ float sm[];
    float* Wt = sm;                 // [147][128] permuted
    float* As = sm + Fm * Hm;       // [64][S_IN]
    int tid = threadIdx.x;

    {
        const float4* src = (const float4*)g_WiT;
        float4* dst = (float4*)Wt;
        for (int i = tid; i < Fm * Hm / 4; i += 128) dst[i] = src[i];
    }
    int row0 = blockIdx.x * 64;
    for (int i = tid; i < 64 * Fm; i += 128) {
        int r = i / Fm, f = i - r * Fm;
        As[r * S_IN + f] = fin[(size_t)(row0 + r) * Fm + f];
    }
    __syncthreads();

    int rg = tid >> 3, cgi = tid & 7;
    int r0 = rg * 4, c0 = cgi * 16;
    unsigned long long acc[32];
#pragma unroll
    for (int i = 0; i < 32; i++) acc[i] = 0ull;

    gemm4x16(Wt, As + r0 * S_IN, S_IN, Fm, cgi, acc);

#pragma unroll
    for (int i = 0; i < 4; i++) {
        float o[16];
#pragma unroll
        for (int j = 0; j < 8; j++) UNPACK2(o[2 * j], o[2 * j + 1], acc[i * 8 + j]);
        size_t base = (size_t)(row0 + r0 + i) * Hm + c0;
        float4* pi = (float4*)(g_inp + base);
        float4* pm = (float4*)(g_msgA + base);
#pragma unroll
        for (int m = 0; m < 4; m++) {
            pi[m] = make_float4(o[4 * m], o[4 * m + 1], o[4 * m + 2], o[4 * m + 3]);
            pm[m] = make_float4(fmaxf(o[4 * m], 0.f), fmaxf(o[4 * m + 1], 0.f),
                                fmaxf(o[4 * m + 2], 0.f), fmaxf(o[4 * m + 3], 0.f));
        }
    }
}

// ---------------------------------------------------------------------------
// agg = gather_sum(msg_in, mapping); msg_out = relu(inp + agg @ Wh^T)
// ---------------------------------------------------------------------------
extern "C" __global__ void __launch_bounds__(128) k_mp(const int* __restrict__ mapping,
                                                       int dir)
{
    const float* msg_in = dir ? g_msgB : g_msgA;
    float* msg_out = dir ? g_msgA : g_msgB;

    extern __shared__ float sm[];
    float* Wt = sm;                 // [128][128] permuted
    float* Ag = sm + Hm * Hm;       // [64][S_AG]
    int tid = threadIdx.x;

    {
        const float4* src = (const float4*)g_WhT;
        float4* dst = (float4*)Wt;
        for (int i = tid; i < Hm * Hm / 4; i += 128) dst[i] = src[i];
    }
    int row0 = blockIdx.x * 64;
    {
        int r = tid >> 1, hb = (tid & 1) * 64;
        int gr = row0 + r, b = gr >> 8;
        const int* mp = mapping + (size_t)gr * Km;
        float4 s[16];
#pragma unroll
        for (int j = 0; j < 16; j++) s[j] = make_float4(0.f, 0.f, 0.f, 0.f);
#pragma unroll
        for (int k = 0; k < Km; k++) {
            const float4* p = (const float4*)(msg_in + (size_t)(b * Em + mp[k]) * Hm + hb);
#pragma unroll
            for (int j = 0; j < 16; j++) {
                float4 v = p[j];
                s[j].x += v.x; s[j].y += v.y; s[j].z += v.z; s[j].w += v.w;
            }
        }
        float* arow = Ag + r * S_AG + hb;
#pragma unroll
        for (int j = 0; j < 16; j++) {
            arow[4 * j + 0] = s[j].x; arow[4 * j + 1] = s[j].y;
            arow[4 * j + 2] = s[j].z; arow[4 * j + 3] = s[j].w;
        }
    }
    __syncthreads();

    int rg = tid >> 3, cgi = tid & 7;
    int r0 = rg * 4, c0 = cgi * 16;
    unsigned long long acc[32];
#pragma unroll
    for (int i = 0; i < 32; i++) acc[i] = 0ull;

    gemm4x16(Wt, Ag + r0 * S_AG, S_AG, Hm, cgi, acc);

#pragma unroll
    for (int i = 0; i < 4; i++) {
        float o[16];
#pragma unroll
        for (int j = 0; j < 8; j++) UNPACK2(o[2 * j], o[2 * j + 1], acc[i * 8 + j]);
        size_t base = (size_t)(row0 + r0 + i) * Hm + c0;
        const float4* pin = (const float4*)(g_inp + base);
        float4* po = (float4*)(msg_out + base);
#pragma unroll
        for (int m = 0; m < 4; m++) {
            float4 iv = pin[m];
            po[m] = make_float4(fmaxf(iv.x + o[4 * m], 0.f),
                                fmaxf(iv.y + o[4 * m + 1], 0.f),
                                fmaxf(iv.z + o[4 * m + 2], 0.f),
                                fmaxf(iv.w + o[4 * m + 3], 0.f));
        }
    }
}

// ---------------------------------------------------------------------------
// m2a gather + concat + relu(cat @ Wo^T + bo) + scatter valid rows
// ---------------------------------------------------------------------------
extern "C" __global__ void __launch_bounds__(256) k_out(const float* __restrict__ af,
                                                        const int* __restrict__ a2b,
                                                        const float* __restrict__ bo,
                                                        const int* __restrict__ ml,
                                                        float* __restrict__ out)
{
    int row0 = blockIdx.x * 64;
    int b = row0 >> 7;
    int a0 = row0 & 127;
    int len = ml[b];
    if (a0 >= len) return;

    extern __shared__ float sm[];
    float* Wt = sm;                       // [261][128] permuted
    float* Ct = sm + CATD * Hm;           // [64][S_CAT]
    float* bs = Ct + 64 * S_CAT;          // [128]
    int tid = threadIdx.x;

    if (tid < 128) bs[tid] = bo[tid];
    {
        const float4* src = (const float4*)g_WoT;
        float4* dst = (float4*)Wt;
        for (int i = tid; i < CATD * Hm / 4; i += 256) dst[i] = src[i];
    }
    for (int i = tid; i < 64 * AFm; i += 256) {
        int r = i / AFm, f = i - r * AFm;
        Ct[r * S_CAT + f] = af[(size_t)(row0 + r) * AFm + f];
    }
    {
        int r = tid >> 2, hb = (tid & 3) * 32;
        int gr = row0 + r;
        const int* gi = a2b + (size_t)gr * Km;
        float4 s[8];
#pragma unroll
        for (int j = 0; j < 8; j++) s[j] = make_float4(0.f, 0.f, 0.f, 0.f);
#pragma unroll
        for (int k = 0; k < Km; k++) {
            const float4* p = (const float4*)(g_msgA + (size_t)(b * Em + gi[k]) * Hm + hb);
#pragma unroll
            for (int j = 0; j < 8; j++) {
                float4 v = p[j];
                s[j].x += v.x; s[j].y += v.y; s[j].z += v.z; s[j].w += v.w;
            }
        }
        float* crow = Ct + r * S_CAT + AFm + hb;
#pragma unroll
        for (int j = 0; j < 8; j++) {
            crow[4 * j + 0] = s[j].x; crow[4 * j + 1] = s[j].y;
            crow[4 * j + 2] = s[j].z; crow[4 * j + 3] = s[j].w;
        }
    }
    __syncthreads();

    int rg = tid >> 3, cgi = tid & 7;
    int r0 = rg * 2, c0 = cgi * 16;
    unsigned long long acc[16];
#pragma unroll
    for (int i = 0; i < 16; i++) acc[i] = 0ull;

    const float* wbase = Wt + cgi * 4;
    const float* Ar = Ct + r0 * S_CAT;
#pragma unroll 2
    for (int k = 0; k < CATD; k++) {
        const float* wrow = wbase + k * Hm;
        ulonglong2 v0 = *(const ulonglong2*)(wrow);
        ulonglong2 v1 = *(const ulonglong2*)(wrow + 32);
        ulonglong2 v2 = *(const ulonglong2*)(wrow + 64);
        ulonglong2 v3 = *(const ulonglong2*)(wrow + 96);
        unsigned long long w0 = v0.x, w1 = v0.y, w2 = v1.x, w3 = v1.y;
        unsigned long long w4 = v2.x, w5 = v2.y, w6 = v3.x, w7 = v3.y;
#pragma unroll
        for (int i = 0; i < 2; i++) {
            unsigned long long av;
            PACK2(av, Ar[i * S_CAT + k]);
            FMA2(acc[i * 8 + 0], av, w0, acc[i * 8 + 0]);
            FMA2(acc[i * 8 + 1], av, w1, acc[i * 8 + 1]);
            FMA2(acc[i * 8 + 2], av, w2, acc[i * 8 + 2]);
            FMA2(acc[i * 8 + 3], av, w3, acc[i * 8 + 3]);
            FMA2(acc[i * 8 + 4], av, w4, acc[i * 8 + 4]);
            FMA2(acc[i * 8 + 5], av, w5, acc[i * 8 + 5]);
            FMA2(acc[i * 8 + 6], av, w6, acc[i * 8 + 6]);
            FMA2(acc[i * 8 + 7], av, w7, acc[i * 8 + 7]);
        }
    }

    int off = g_off[b];
#pragma unroll
    for (int i = 0; i < 2; i++) {
        int a = a0 + r0 + i;
        if (a < len) {
            float o[16];
#pragma unroll
            for (int j = 0; j < 8; j++) UNPACK2(o[2 * j], o[2 * j + 1], acc[i * 8 + j]);
            float4* po = (float4*)(out + (size_t)(off + a) * Hm + c0);
#pragma unroll
            for (int m = 0; m < 4; m++) {
                po[m] = make_float4(fmaxf(o[4 * m + 0] + bs[c0 + 4 * m + 0], 0.f),
                                    fmaxf(o[4 * m + 1] + bs[c0 + 4 * m + 1], 0.f),
                                    fmaxf(o[4 * m + 2] + bs[c0 + 4 * m + 2], 0.f),
                                    fmaxf(o[4 * m + 3] + bs[c0 + 4 * m + 3], 0.f));
            }
        }
    }
}

// ---------------------------------------------------------------------------
extern "C" void kernel_launch(void* const* d_in, const int* in_sizes, int n_in,
                              void* d_out, int out_size)
{
    const float* af      = (const float*)d_in[0];
    const float* fin     = (const float*)d_in[1];
    const int*   a2b     = (const int*)d_in[2];
    const int*   mapping = (const int*)d_in[3];
    const int*   ml      = (const int*)d_in[5];
    const float* Wi      = (const float*)d_in[6];
    const float* Wh      = (const float*)d_in[7];
    const float* Wo      = (const float*)d_in[8];
    const float* bo      = (const float*)d_in[9];
    float* out = (float*)d_out;
    float* maskbase = out + (size_t)out_size - (size_t)Bm * Am;

    int smA = (Fm * Hm + 64 * S_IN) * 4;            // 113,408 B
    int smM = (Hm * Hm + 64 * S_AG) * 4;            //  99,584 B
    int smO = (CATD * Hm + 64 * S_CAT + 128) * 4;   // 203,008 B
    cudaFuncSetAttribute(k_wi,  cudaFuncAttributeMaxDynamicSharedMemorySize, smA);
    cudaFuncSetAttribute(k_mp,  cudaFuncAttributeMaxDynamicSharedMemorySize, smM);
    cudaFuncSetAttribute(k_out, cudaFuncAttributeMaxDynamicSharedMemorySize, smO);

    k_scan<<<1, 512>>>(ml, maskbase);
    k_tw<<<(Fm * Hm + Hm * Hm + CATD * Hm + 255) / 256, 256>>>(Wi, Wh, Wo);
    k_wi<<<(Bm * Em) / 64, 128, smA>>>(fin);
    k_mp<<<(Bm * Em) / 64, 128, smM>>>(mapping, 0);   // msgA -> msgB
    k_mp<<<(Bm * Em) / 64, 128, smM>>>(mapping, 1);   // msgB -> msgA
    k_out<<<(Bm * Am) / 64, 256, smO>>>(af, a2b, bo, ml, out);
}

// round 8
// speedup vs baseline: 5.5523x; 1.1787x over previous
#include <cuda_runtime.h>
#include <cuda_bf16.h>
#include <mma.h>
#include <cstdint>

using namespace nvcuda;

#define Bm 512
#define Em 256
#define Am 128
#define Km 6
#define Fm 147
#define AFm 133
#define Hm 128

#define KWI 160          // 147 padded
#define KWO 272          // 133 af + 11 zero + 128 m2a
#define LDA_WI 168
#define LD_128 136
#define LD_144 152

// f32 scratch
__device__ float g_inp [Bm * Em * Hm];
__device__ float g_msgA[Bm * Em * Hm];
__device__ float g_msgB[Bm * Em * Hm];
__device__ int   g_off[Bm];
// pre-split hi/lo bf16 weights, row-major [128][K]
__device__ __align__(16) __nv_bfloat16 g_WiH[128 * KWI];
__device__ __align__(16) __nv_bfloat16 g_WiL[128 * KWI];
__device__ __align__(16) __nv_bfloat16 g_WhH[128 * 128];
__device__ __align__(16) __nv_bfloat16 g_WhL[128 * 128];
__device__ __align__(16) __nv_bfloat16 g_WoH[128 * KWO];
__device__ __align__(16) __nv_bfloat16 g_WoL[128 * KWO];

// write 4 consecutive cols (c..c+3) of row r into hi/lo bf16 smem tiles
__device__ __forceinline__ void wr4(__nv_bfloat16* AH, __nv_bfloat16* AL,
                                    int ldm, int r, int c, float4 v) {
    int o = r * ldm + c;
    __nv_bfloat16 h0 = __float2bfloat16_rn(v.x), h1 = __float2bfloat16_rn(v.y),
                  h2 = __float2bfloat16_rn(v.z), h3 = __float2bfloat16_rn(v.w);
    uint2 hp;
    hp.x = (uint32_t)__bfloat16_as_ushort(h0) | ((uint32_t)__bfloat16_as_ushort(h1) << 16);
    hp.y = (uint32_t)__bfloat16_as_ushort(h2) | ((uint32_t)__bfloat16_as_ushort(h3) << 16);
    *(uint2*)(AH + o) = hp;
    __nv_bfloat16 l0 = __float2bfloat16_rn(v.x - __bfloat162float(h0));
    __nv_bfloat16 l1 = __float2bfloat16_rn(v.y - __bfloat162float(h1));
    __nv_bfloat16 l2 = __float2bfloat16_rn(v.z - __bfloat162float(h2));
    __nv_bfloat16 l3 = __float2bfloat16_rn(v.w - __bfloat162float(h3));
    uint2 lp;
    lp.x = (uint32_t)__bfloat16_as_ushort(l0) | ((uint32_t)__bfloat16_as_ushort(l1) << 16);
    lp.y = (uint32_t)__bfloat16_as_ushort(l2) | ((uint32_t)__bfloat16_as_ushort(l3) << 16);
    *(uint2*)(AL + o) = lp;
}

typedef wmma::fragment<wmma::matrix_a, 16, 16, 16, __nv_bfloat16, wmma::row_major> FragA;
typedef wmma::fragment<wmma::matrix_b, 16, 16, 16, __nv_bfloat16, wmma::col_major> FragB;
typedef wmma::fragment<wmma::accumulator, 16, 16, 16, float> FragC;

// hi/lo 3-pass MMA over nks K-steps; warp owns rows [w*16,w*16+16) x N=128
__device__ __forceinline__ void mma_tile(const __nv_bfloat16* AH, const __nv_bfloat16* AL, int ldA,
                                         const __nv_bfloat16* BH, const __nv_bfloat16* BL, int ldB,
                                         int nks, int w, FragC c[8]) {
    for (int ks = 0; ks < nks; ks++) {
        FragA ah, al;
        wmma::load_matrix_sync(ah, AH + w * 16 * ldA + ks * 16, ldA);
        wmma::load_matrix_sync(al, AL + w * 16 * ldA + ks * 16, ldA);
#pragma unroll
        for (int nt = 0; nt < 8; nt++) {
            FragB bh, bl;
            wmma::load_matrix_sync(bh, BH + nt * 16 * ldB + ks * 16, ldB);
            wmma::load_matrix_sync(bl, BL + nt * 16 * ldB + ks * 16, ldB);
            wmma::mma_sync(c[nt], ah, bh, c[nt]);
            wmma::mma_sync(c[nt], ah, bl, c[nt]);
            wmma::mma_sync(c[nt], al, bh, c[nt]);
        }
    }
}

// ---------------------------------------------------------------------------
extern "C" __global__ void __launch_bounds__(512) k_scan(const int* __restrict__ ml,
                                                         float* __restrict__ maskbase)
{
    __shared__ int s[512];
    int t = threadIdx.x;
    int v = ml[t];
    s[t] = v;
    __syncthreads();
    for (int off = 1; off < 512; off <<= 1) {
        int u = (t >= off) ? s[t - off] : 0;
        __syncthreads();
        s[t] += u;
        __syncthreads();
    }
    g_off[t] = s[t] - v;
    for (int i = t; i < Bm * Am; i += 512) {
        int b = i >> 7, a = i & 127;
        maskbase[i] = (a < ml[b]) ? 1.0f : 0.0f;
    }
}

// ---------------------------------------------------------------------------
// weight split: Wi -> [128][160], Wh -> [128][128],
// Wo -> [128][272] (k<133: af part, 133..143: 0, 144..271: m2a part)
// ---------------------------------------------------------------------------
extern "C" __global__ void __launch_bounds__(256) k_tw(const float* __restrict__ Wi,
                                                       const float* __restrict__ Wh,
                                                       const float* __restrict__ Wo)
{
    int idx = blockIdx.x * 256 + threadIdx.x;
    float v; __nv_bfloat16 *ph, *pl; int o;
    if (idx < 128 * KWI) {
        int n = idx / KWI, k = idx - n * KWI;
        v = (k < Fm) ? Wi[n * Fm + k] : 0.f;
        ph = g_WiH; pl = g_WiL; o = idx;
    } else if (idx < 128 * KWI + 128 * 128) {
        int p = idx - 128 * KWI;
        v = Wh[p];
        ph = g_WhH; pl = g_WhL; o = p;
    } else if (idx < 128 * (KWI + 128 + KWO)) {
        int p = idx - 128 * KWI - 128 * 128;
        int n = p / KWO, k = p - n * KWO;
        if (k < AFm)        v = Wo[n * 261 + k];
        else if (k >= 144)  v = Wo[n * 261 + k - 11];
        else                v = 0.f;
        ph = g_WoH; pl = g_WoL; o = p;
    } else return;
    __nv_bfloat16 h = __float2bfloat16_rn(v);
    ph[o] = h;
    pl[o] = __float2bfloat16_rn(v - __bfloat162float(h));
}

// ---------------------------------------------------------------------------
// k_wi: inp = fin @ Wi^T ; msgA = relu(inp).  M=128/block, grid 1024.
// smem: AH/AL ldm 168 (86016B) | BH/BL ldm 168 (86016B); C f32 ldm 136 overlaps A
// ---------------------------------------------------------------------------
#define WI_AH 0
#define WI_AL (128 * LDA_WI)
#define WI_BH (2 * 128 * LDA_WI)
#define WI_BL (3 * 128 * LDA_WI)
#define WI_SMB (4 * 128 * LDA_WI * 2)

extern "C" __global__ void __launch_bounds__(256) k_wi(const float* __restrict__ fin)
{
    extern __shared__ __nv_bfloat16 sm[];
    int tid = threadIdx.x, w = tid >> 5;
    int row0 = blockIdx.x * 128;

    // stage B
    {
        const uint4* sh = (const uint4*)g_WiH;
        const uint4* sl = (const uint4*)g_WiL;
        for (int i = tid; i < 128 * KWI / 8; i += 256) {
            int r = i / (KWI / 8), ch = i - r * (KWI / 8);
            *(uint4*)(sm + WI_BH + r * LDA_WI + ch * 8) = sh[i];
            *(uint4*)(sm + WI_BL + r * LDA_WI + ch * 8) = sl[i];
        }
    }
    // stage A (2 threads/row)
    {
        int r = tid >> 1, h = tid & 1;
        const float* fr = fin + (size_t)(row0 + r) * Fm;
        for (int c = h * 80; c < h * 80 + 80; c += 4) {
            float4 v;
            v.x = (c + 0 < Fm) ? fr[c + 0] : 0.f;
            v.y = (c + 1 < Fm) ? fr[c + 1] : 0.f;
            v.z = (c + 2 < Fm) ? fr[c + 2] : 0.f;
            v.w = (c + 3 < Fm) ? fr[c + 3] : 0.f;
            wr4(sm + WI_AH, sm + WI_AL, LDA_WI, r, c, v);
        }
    }
    __syncthreads();

    FragC c[8];
#pragma unroll
    for (int nt = 0; nt < 8; nt++) wmma::fill_fragment(c[nt], 0.f);
    mma_tile(sm + WI_AH, sm + WI_AL, LDA_WI, sm + WI_BH, sm + WI_BL, LDA_WI, KWI / 16, w, c);
    __syncthreads();

    float* Cs = (float*)sm;
#pragma unroll
    for (int nt = 0; nt < 8; nt++)
        wmma::store_matrix_sync(Cs + w * 16 * LD_128 + nt * 16, c[nt], LD_128, wmma::mem_row_major);
    __syncthreads();

    {
        int r = tid >> 1, hb = (tid & 1) * 64;
        const float* cr = Cs + r * LD_128 + hb;
        size_t base = (size_t)(row0 + r) * Hm + hb;
        float4* pi = (float4*)(g_inp + base);
        float4* pm = (float4*)(g_msgA + base);
#pragma unroll
        for (int q = 0; q < 16; q++) {
            float x0 = cr[4 * q], x1 = cr[4 * q + 1], x2 = cr[4 * q + 2], x3 = cr[4 * q + 3];
            pi[q] = make_float4(x0, x1, x2, x3);
            pm[q] = make_float4(fmaxf(x0, 0.f), fmaxf(x1, 0.f), fmaxf(x2, 0.f), fmaxf(x3, 0.f));
        }
    }
}

// ---------------------------------------------------------------------------
// k_mp: agg = gather6(msg_in); msg_out = relu(inp + agg @ Wh^T). grid 1024.
// ---------------------------------------------------------------------------
#define MP_AH 0
#define MP_AL (128 * LD_128)
#define MP_BH (2 * 128 * LD_128)
#define MP_BL (3 * 128 * LD_128)
#define MP_SMB (4 * 128 * LD_128 * 2)

extern "C" __global__ void __launch_bounds__(256) k_mp(const int* __restrict__ mapping, int dir)
{
    const float* msg_in = dir ? g_msgB : g_msgA;
    float* msg_out = dir ? g_msgA : g_msgB;

    extern __shared__ __nv_bfloat16 sm[];
    int tid = threadIdx.x, w = tid >> 5;
    int row0 = blockIdx.x * 128;
    int bmol = blockIdx.x >> 1;

    // stage B
    {
        const uint4* sh = (const uint4*)g_WhH;
        const uint4* sl = (const uint4*)g_WhL;
        for (int i = tid; i < 128 * 128 / 8; i += 256) {
            int r = i >> 4, ch = i & 15;
            *(uint4*)(sm + MP_BH + r * LD_128 + ch * 8) = sh[i];
            *(uint4*)(sm + MP_BL + r * LD_128 + ch * 8) = sl[i];
        }
    }
    // gather (2 threads/row)
    {
        int r = tid >> 1, hb = (tid & 1) * 64;
        int gr = row0 + r;
        const int* mp = mapping + (size_t)gr * Km;
        int i0 = mp[0], i1 = mp[1], i2 = mp[2], i3 = mp[3], i4 = mp[4], i5 = mp[5];
        const float* mb = msg_in + (size_t)bmol * Em * Hm + hb;
        const float4* p0 = (const float4*)(mb + (size_t)i0 * Hm);
        const float4* p1 = (const float4*)(mb + (size_t)i1 * Hm);
        const float4* p2 = (const float4*)(mb + (size_t)i2 * Hm);
        const float4* p3 = (const float4*)(mb + (size_t)i3 * Hm);
        const float4* p4 = (const float4*)(mb + (size_t)i4 * Hm);
        const float4* p5 = (const float4*)(mb + (size_t)i5 * Hm);
#pragma unroll
        for (int j = 0; j < 16; j++) {
            float4 a = p0[j], b = p1[j], c = p2[j], d = p3[j], e = p4[j], f = p5[j];
            float4 s = make_float4(a.x + b.x + c.x + d.x + e.x + f.x,
                                   a.y + b.y + c.y + d.y + e.y + f.y,
                                   a.z + b.z + c.z + d.z + e.z + f.z,
                                   a.w + b.w + c.w + d.w + e.w + f.w);
            wr4(sm + MP_AH, sm + MP_AL, LD_128, r, hb + 4 * j, s);
        }
    }
    __syncthreads();

    FragC c[8];
#pragma unroll
    for (int nt = 0; nt < 8; nt++) wmma::fill_fragment(c[nt], 0.f);
    mma_tile(sm + MP_AH, sm + MP_AL, LD_128, sm + MP_BH, sm + MP_BL, LD_128, 8, w, c);
    __syncthreads();

    float* Cs = (float*)sm;
#pragma unroll
    for (int nt = 0; nt < 8; nt++)
        wmma::store_matrix_sync(Cs + w * 16 * LD_128 + nt * 16, c[nt], LD_128, wmma::mem_row_major);
    __syncthreads();

    {
        int r = tid >> 1, hb = (tid & 1) * 64;
        const float* cr = Cs + r * LD_128 + hb;
        size_t base = (size_t)(row0 + r) * Hm + hb;
        const float4* pin = (const float4*)(g_inp + base);
        float4* po = (float4*)(msg_out + base);
#pragma unroll
        for (int q = 0; q < 16; q++) {
            float4 iv = pin[q];
            po[q] = make_float4(fmaxf(iv.x + cr[4 * q], 0.f),
                                fmaxf(iv.y + cr[4 * q + 1], 0.f),
                                fmaxf(iv.z + cr[4 * q + 2], 0.f),
                                fmaxf(iv.w + cr[4 * q + 3], 0.f));
        }
    }
}

// ---------------------------------------------------------------------------
// k_out: cat = [af | 0*11 | m2a]; atoms_h = relu(cat @ WoT + bo); scatter.
// A1 (af, K=144, ldm 152) and A2 (m2a, K=128, ldm 136) staged separately;
// B buffer (ldm 152) reused across 2 chunks. grid 512.
// ---------------------------------------------------------------------------
#define KO_A1H 0
#define KO_A1L (128 * LD_144)
#define KO_A2H (2 * 128 * LD_144)
#define KO_A2L (2 * 128 * LD_144 + 128 * LD_128)
#define KO_BH  (2 * 128 * LD_144 + 2 * 128 * LD_128)
#define KO_BL  (3 * 128 * LD_144 + 2 * 128 * LD_128)
#define KO_BIAS (4 * 128 * LD_144 + 2 * 128 * LD_128)   // f32[128] -> 256 bf16 slots
#define KO_SMB ((4 * 128 * LD_144 + 2 * 128 * LD_128) * 2 + 512)

extern "C" __global__ void __launch_bounds__(256) k_out(const float* __restrict__ af,
                                                        const int* __restrict__ a2b,
                                                        const float* __restrict__ bo,
                                                        const int* __restrict__ ml,
                                                        float* __restrict__ out)
{
    extern __shared__ __nv_bfloat16 sm[];
    int tid = threadIdx.x, w = tid >> 5;
    int b = blockIdx.x;
    int row0 = b * 128;

    if (tid < 128) ((float*)(sm + KO_BIAS))[tid] = bo[tid];

    int r = tid >> 1, h = tid & 1, hb = h * 64;
    // gather m2a -> A2 (hi/lo)
    {
        int gr = row0 + r;
        const int* gi = a2b + (size_t)gr * Km;
        int i0 = gi[0], i1 = gi[1], i2 = gi[2], i3 = gi[3], i4 = gi[4], i5 = gi[5];
        const float* mb = g_msgA + (size_t)b * Em * Hm + hb;
        const float4* p0 = (const float4*)(mb + (size_t)i0 * Hm);
        const float4* p1 = (const float4*)(mb + (size_t)i1 * Hm);
        const float4* p2 = (const float4*)(mb + (size_t)i2 * Hm);
        const float4* p3 = (const float4*)(mb + (size_t)i3 * Hm);
        const float4* p4 = (const float4*)(mb + (size_t)i4 * Hm);
        const float4* p5 = (const float4*)(mb + (size_t)i5 * Hm);
#pragma unroll
        for (int j = 0; j < 16; j++) {
            float4 a = p0[j], bb = p1[j], c = p2[j], d = p3[j], e = p4[j], f = p5[j];
            float4 s = make_float4(a.x + bb.x + c.x + d.x + e.x + f.x,
                                   a.y + bb.y + c.y + d.y + e.y + f.y,
                                   a.z + bb.z + c.z + d.z + e.z + f.z,
                                   a.w + bb.w + c.w + d.w + e.w + f.w);
            wr4(sm + KO_A2H, sm + KO_A2L, LD_128, r, hb + 4 * j, s);
        }
    }
    // stage A1 (af + zero pad to 144)
    {
        const float* ar = af + (size_t)(row0 + r) * AFm;
        for (int c = h * 72; c < h * 72 + 72; c += 4) {
            float4 v;
            v.x = (c + 0 < AFm) ? ar[c + 0] : 0.f;
            v.y = (c + 1 < AFm) ? ar[c + 1] : 0.f;
            v.z = (c + 2 < AFm) ? ar[c + 2] : 0.f;
            v.w = (c + 3 < AFm) ? ar[c + 3] : 0.f;
            wr4(sm + KO_A1H, sm + KO_A1L, LD_144, r, c, v);
        }
    }
    // stage B chunk1 (cols 0..143 of g_Wo)
    {
        const uint4* sh = (const uint4*)g_WoH;
        const uint4* sl = (const uint4*)g_WoL;
        for (int i = tid; i < 128 * 18; i += 256) {
            int rr = i / 18, ch = i - rr * 18;
            uint4 vh = sh[rr * (KWO / 8) + ch];
            uint4 vl = sl[rr * (KWO / 8) + ch];
            *(uint4*)(sm + KO_BH + rr * LD_144 + ch * 8) = vh;
            *(uint4*)(sm + KO_BL + rr * LD_144 + ch * 8) = vl;
        }
    }
    __syncthreads();

    FragC c[8];
#pragma unroll
    for (int nt = 0; nt < 8; nt++) wmma::fill_fragment(c[nt], 0.f);
    mma_tile(sm + KO_A1H, sm + KO_A1L, LD_144, sm + KO_BH, sm + KO_BL, LD_144, 9, w, c);
    __syncthreads();

    // stage B chunk2 (cols 144..271)
    {
        const uint4* sh = (const uint4*)g_WoH;
        const uint4* sl = (const uint4*)g_WoL;
        for (int i = tid; i < 128 * 16; i += 256) {
            int rr = i >> 4, ch = i & 15;
            uint4 vh = sh[rr * (KWO / 8) + 18 + ch];
            uint4 vl = sl[rr * (KWO / 8) + 18 + ch];
            *(uint4*)(sm + KO_BH + rr * LD_144 + ch * 8) = vh;
            *(uint4*)(sm + KO_BL + rr * LD_144 + ch * 8) = vl;
        }
    }
    __syncthreads();

    mma_tile(sm + KO_A2H, sm + KO_A2L, LD_128, sm + KO_BH, sm + KO_BL, LD_144, 8, w, c);
    __syncthreads();

    float* Cs = (float*)sm;
#pragma unroll
    for (int nt = 0; nt < 8; nt++)
        wmma::store_matrix_sync(Cs + w * 16 * LD_128 + nt * 16, c[nt], LD_128, wmma::mem_row_major);
    __syncthreads();

    {
        int len = ml[b];
        if (r < len) {
            const float* cr = Cs + r * LD_128 + hb;
            const float* bs = (const float*)(sm + KO_BIAS) + hb;
            float4* po = (float4*)(out + (size_t)(g_off[b] + r) * Hm + hb);
#pragma unroll
            for (int q = 0; q < 16; q++)
                po[q] = make_float4(fmaxf(cr[4 * q + 0] + bs[4 * q + 0], 0.f),
                                    fmaxf(cr[4 * q + 1] + bs[4 * q + 1], 0.f),
                                    fmaxf(cr[4 * q + 2] + bs[4 * q + 2], 0.f),
                                    fmaxf(cr[4 * q + 3] + bs[4 * q + 3], 0.f));
        }
    }
}

// ---------------------------------------------------------------------------
extern "C" void kernel_launch(void* const* d_in, const int* in_sizes, int n_in,
                              void* d_out, int out_size)
{
    const float* af      = (const float*)d_in[0];
    const float* fin     = (const float*)d_in[1];
    const int*   a2b     = (const int*)d_in[2];
    const int*   mapping = (const int*)d_in[3];
    const int*   ml      = (const int*)d_in[5];
    const float* Wi      = (const float*)d_in[6];
    const float* Wh      = (const float*)d_in[7];
    const float* Wo      = (const float*)d_in[8];
    const float* bo      = (const float*)d_in[9];
    float* out = (float*)d_out;
    float* maskbase = out + (size_t)out_size - (size_t)Bm * Am;

    cudaFuncSetAttribute(k_wi,  cudaFuncAttributeMaxDynamicSharedMemorySize, WI_SMB);
    cudaFuncSetAttribute(k_mp,  cudaFuncAttributeMaxDynamicSharedMemorySize, MP_SMB);
    cudaFuncSetAttribute(k_out, cudaFuncAttributeMaxDynamicSharedMemorySize, KO_SMB);

    k_scan<<<1, 512>>>(ml, maskbase);
    k_tw<<<(128 * (KWI + 128 + KWO) + 255) / 256, 256>>>(Wi, Wh, Wo);
    k_wi<<<1024, 256, WI_SMB>>>(fin);
    k_mp<<<1024, 256, MP_SMB>>>(mapping, 0);   // msgA -> msgB
    k_mp<<<1024, 256, MP_SMB>>>(mapping, 1);   // msgB -> msgA
    k_out<<<512, 256, KO_SMB>>>(af, a2b, bo, ml, out);
}